// round 3
// baseline (speedup 1.0000x reference)
#include <cuda_runtime.h>
#include <cstdint>

#define NN 8192u
#define MD 8193u
#define MM 67125249u          // 8193*8193
#define BIAS_START 67117056u  // 8192*8193 (start of last row within a matrix)
#define DIAG_STRIDE 8194u     // diag element i lives at i*(MD+1)
#define CLCU 16384u           // 2*NN floats of cl/cu before the matrices
#define TOTAL 134266882u      // CLCU + 2*MM
#define EPS_ALPHA 1e-5f

struct Relax {
    float cl, cu, dl, du, bl, bu;
};

__device__ __forceinline__ Relax relax(float l, float u)
{
    float den_ul = (u > l)    ? (u - l)    : 1.0f;
    float den_6l = (l < 6.0f) ? (6.0f - l) : 1.0f;
    float u_safe = (u > 0.0f) ? u          : 1.0f;

    bool mA = (u > 0.0f) && (u <= 6.0f) && (l >= 0.0f);
    bool mB = (u > 0.0f) && (u <= 6.0f) && (l <  0.0f);
    bool mC = (u > 6.0f) && (l <= 0.0f);
    bool mD = (u > 6.0f) && (l >  0.0f) && (l <= 6.0f);
    bool mE = (l > 6.0f);

    float alpha_B = (u < -l) ? EPS_ALPHA : 1.0f;
    float lam_B   = u / den_ul;
    float aU_C    = ((u - 6.0f) < (6.0f - l)) ? (6.0f / den_6l) : EPS_ALPHA;
    float aL_C    = (u < -l) ? EPS_ALPHA : (6.0f / u_safe);
    float aU_D    = ((u - 6.0f) < (6.0f - l)) ? 1.0f : EPS_ALPHA;
    float aL_D    = (6.0f - l) / den_ul;

    float fA = mA ? 1.0f : 0.0f;
    float fB = mB ? 1.0f : 0.0f;
    float fC = mC ? 1.0f : 0.0f;
    float fD = mD ? 1.0f : 0.0f;
    float fE = mE ? 1.0f : 0.0f;

    Relax r;
    r.du = fA * 1.0f + fB * lam_B   + fC * aU_C + fD * aU_D;
    r.dl = fA * 1.0f + fB * alpha_B + fC * aL_C + fD * aL_D;
    r.bu = fB * (-lam_B * l)
         + fC * (6.0f * (1.0f - aU_C))
         + fD * (6.0f * (1.0f - aU_D))
         + fE * 6.0f;
    r.bl = fD * (l * (1.0f - aL_D)) + fE * 6.0f;
    r.cu = fA * u + fB * u
         + fC * (6.0f + aU_C * (u - 6.0f))
         + fD * (6.0f + aU_D * (u - 6.0f))
         + fE * 6.0f;
    r.cl = fA * l + fB * (alpha_B * l) + fC * (aL_C * l)
         + fD * l + fE * 6.0f;
    return r;
}

// Value of one in-matrix element at offset p (0 <= p < MM) for matrix L (isL) or U.
__device__ __forceinline__ float mat_value(unsigned p, bool isL,
                                           const float* __restrict__ lower,
                                           const float* __restrict__ upper)
{
    if (p >= BIAS_START) {
        unsigned col = p - BIAS_START;
        if (col == NN) return 1.0f;          // [-1,-1] corner
        Relax r = relax(lower[col], upper[col]);
        return isL ? r.bl : r.bu;
    }
    unsigned row = p / DIAG_STRIDE;
    if (p == row * DIAG_STRIDE) {
        Relax r = relax(lower[row], upper[row]);
        return isL ? r.dl : r.du;
    }
    return 0.0f;
}

__device__ __forceinline__ float out_value(unsigned oe,
                                           const float* __restrict__ lower,
                                           const float* __restrict__ upper)
{
    if (oe < CLCU) {
        unsigned i = oe & (NN - 1u);
        Relax r = relax(lower[i], upper[i]);
        return (oe < NN) ? r.cl : r.cu;
    }
    unsigned r = oe - CLCU;
    if (r < MM) return mat_value(r, true, lower, upper);
    return mat_value(r - MM, false, lower, upper);
}

// Each thread owns a 128-byte (32-float) region.
__global__ void relu6_fused128(const float* __restrict__ lower,
                               const float* __restrict__ upper,
                               float* __restrict__ out)
{
    unsigned t = blockIdx.x * blockDim.x + threadIdx.x;
    unsigned o = t * 32u;
    if (o >= TOTAL) return;

    // Fast path: region fully inside one matrix and contains no diag/bias element.
    unsigned r = o - CLCU;                      // only meaningful when o >= CLCU
    bool inL = (o >= CLCU) & (r + 32u <= MM);
    bool inU = (o >= CLCU) & (r >= MM) & (r + 32u <= 2u * MM);
    unsigned p = inU ? (r - MM) : r;

    unsigned q = (p + 31u) / DIAG_STRIDE;       // constant divide -> umulhi
    bool hasDiag = (q * DIAG_STRIDE >= p);      // a multiple of 8194 in [p, p+32)
    bool hasBias = (p + 31u >= BIAS_START);

    if ((inL | inU) & !hasDiag & !hasBias) {
        float4 z = make_float4(0.f, 0.f, 0.f, 0.f);
        float4* dst = reinterpret_cast<float4*>(out + o);
        #pragma unroll
        for (int j = 0; j < 8; ++j) dst[j] = z;
        return;
    }

    // Slow path: per-element (cl/cu region, diag/bias regions, boundaries, tail).
    unsigned end = (o + 32u < TOTAL) ? (o + 32u) : TOTAL;
    for (unsigned e = o; e < end; ++e)
        out[e] = out_value(e, lower, upper);
}

extern "C" void kernel_launch(void* const* d_in, const int* in_sizes, int n_in,
                              void* d_out, int out_size)
{
    const float* lower = (const float*)d_in[0];
    const float* upper = (const float*)d_in[1];
    float* out = (float*)d_out;

    unsigned nregions = (TOTAL + 31u) / 32u;
    unsigned threads = 256u;
    unsigned blocks = (nregions + threads - 1u) / threads;
    relu6_fused128<<<blocks, threads>>>(lower, upper, out);
}

// round 4
// speedup vs baseline: 2.3128x; 2.3128x over previous
#include <cuda_runtime.h>
#include <cstdint>

#define NN 8192u
#define MD 8193u
#define MM 67125249u          // 8193*8193
#define BIAS_START 67117056u  // 8192*8193 (start of last row within a matrix)
#define DIAG_STRIDE 8194u     // diag element i lives at i*(MD+1)
#define CLCU 16384u           // 2*NN floats of cl/cu before the matrices
#define TOTAL 134266882u      // CLCU + 2*MM
#define CHUNK 128u            // floats per warp-chunk (512B, one STG.128 per lane)
#define CPW 4u                // warp-chunks per warp
#define EPS_ALPHA 1e-5f

struct Relax {
    float cl, cu, dl, du, bl, bu;
};

__device__ __forceinline__ Relax relax(float l, float u)
{
    float den_ul = (u > l)    ? (u - l)    : 1.0f;
    float den_6l = (l < 6.0f) ? (6.0f - l) : 1.0f;
    float u_safe = (u > 0.0f) ? u          : 1.0f;

    bool mA = (u > 0.0f) && (u <= 6.0f) && (l >= 0.0f);
    bool mB = (u > 0.0f) && (u <= 6.0f) && (l <  0.0f);
    bool mC = (u > 6.0f) && (l <= 0.0f);
    bool mD = (u > 6.0f) && (l >  0.0f) && (l <= 6.0f);
    bool mE = (l > 6.0f);

    float alpha_B = (u < -l) ? EPS_ALPHA : 1.0f;
    float lam_B   = u / den_ul;
    float aU_C    = ((u - 6.0f) < (6.0f - l)) ? (6.0f / den_6l) : EPS_ALPHA;
    float aL_C    = (u < -l) ? EPS_ALPHA : (6.0f / u_safe);
    float aU_D    = ((u - 6.0f) < (6.0f - l)) ? 1.0f : EPS_ALPHA;
    float aL_D    = (6.0f - l) / den_ul;

    float fA = mA ? 1.0f : 0.0f;
    float fB = mB ? 1.0f : 0.0f;
    float fC = mC ? 1.0f : 0.0f;
    float fD = mD ? 1.0f : 0.0f;
    float fE = mE ? 1.0f : 0.0f;

    Relax r;
    r.du = fA * 1.0f + fB * lam_B   + fC * aU_C + fD * aU_D;
    r.dl = fA * 1.0f + fB * alpha_B + fC * aL_C + fD * aL_D;
    r.bu = fB * (-lam_B * l)
         + fC * (6.0f * (1.0f - aU_C))
         + fD * (6.0f * (1.0f - aU_D))
         + fE * 6.0f;
    r.bl = fD * (l * (1.0f - aL_D)) + fE * 6.0f;
    r.cu = fA * u + fB * u
         + fC * (6.0f + aU_C * (u - 6.0f))
         + fD * (6.0f + aU_D * (u - 6.0f))
         + fE * 6.0f;
    r.cl = fA * l + fB * (alpha_B * l) + fC * (aL_C * l)
         + fD * l + fE * 6.0f;
    return r;
}

__device__ __forceinline__ float mat_value(unsigned p, bool isL,
                                           const float* __restrict__ lower,
                                           const float* __restrict__ upper)
{
    if (p >= BIAS_START) {
        unsigned col = p - BIAS_START;
        if (col == NN) return 1.0f;          // [-1,-1] corner
        Relax r = relax(lower[col], upper[col]);
        return isL ? r.bl : r.bu;
    }
    unsigned row = p / DIAG_STRIDE;
    if (p == row * DIAG_STRIDE) {
        Relax r = relax(lower[row], upper[row]);
        return isL ? r.dl : r.du;
    }
    return 0.0f;
}

__device__ __forceinline__ float out_value(unsigned oe,
                                           const float* __restrict__ lower,
                                           const float* __restrict__ upper)
{
    if (oe < CLCU) {
        unsigned i = oe & (NN - 1u);
        Relax r = relax(lower[i], upper[i]);
        return (oe < NN) ? r.cl : r.cu;
    }
    unsigned r = oe - CLCU;
    if (r < MM) return mat_value(r, true, lower, upper);
    return mat_value(r - MM, false, lower, upper);
}

// Warp-uniform classification; coalesced float4 stores; CPW chunks per warp.
__global__ void relu6_warp(const float* __restrict__ lower,
                           const float* __restrict__ upper,
                           float* __restrict__ out)
{
    unsigned gtid = blockIdx.x * blockDim.x + threadIdx.x;
    unsigned warp = gtid >> 5;
    unsigned lane = gtid & 31u;
    unsigned c0 = warp * CPW;

    #pragma unroll
    for (unsigned k = 0; k < CPW; ++k) {
        unsigned o = (c0 + k) * CHUNK;               // chunk start (float offset)
        if (o >= TOTAL) return;

        // Warp-uniform zero test for [o, o+CHUNK)
        unsigned r = o - CLCU;                       // valid when o >= CLCU
        bool inL = (o >= CLCU) & (r + CHUNK <= MM);
        bool inU = (o >= CLCU) & (r >= MM) & (r + CHUNK <= 2u * MM);
        unsigned p = inU ? (r - MM) : r;
        unsigned q = (p + (CHUNK - 1u)) / DIAG_STRIDE;
        bool hasDiag = (q * DIAG_STRIDE >= p);       // multiple of 8194 in chunk
        bool hasBias = (p + (CHUNK - 1u) >= BIAS_START);

        unsigned e = o + lane * 4u;                  // this lane's float4
        if ((inL | inU) & !hasDiag & !hasBias) {
            float4 z = make_float4(0.f, 0.f, 0.f, 0.f);
            __stcs(reinterpret_cast<float4*>(out + e), z);
        } else if (e + 4u <= TOTAL) {
            float4 v;
            v.x = out_value(e + 0u, lower, upper);
            v.y = out_value(e + 1u, lower, upper);
            v.z = out_value(e + 2u, lower, upper);
            v.w = out_value(e + 3u, lower, upper);
            __stcs(reinterpret_cast<float4*>(out + e), v);
        } else {
            for (unsigned j = e; j < TOTAL; ++j)
                out[j] = out_value(j, lower, upper);
        }
    }
}

extern "C" void kernel_launch(void* const* d_in, const int* in_sizes, int n_in,
                              void* d_out, int out_size)
{
    const float* lower = (const float*)d_in[0];
    const float* upper = (const float*)d_in[1];
    float* out = (float*)d_out;

    unsigned nchunks = (TOTAL + CHUNK - 1u) / CHUNK;     // 1048961
    unsigned nwarps  = (nchunks + CPW - 1u) / CPW;       // 262241
    unsigned threads = 512u;
    unsigned blocks  = (nwarps * 32u + threads - 1u) / threads;
    relu6_warp<<<blocks, threads>>>(lower, upper, out);
}

// round 6
// speedup vs baseline: 2.3563x; 1.0188x over previous
#include <cuda_runtime.h>
#include <cstdint>

#define NN 8192u
#define MD 8193u
#define MM 67125249u           // 8193*8193
#define BIAS_START 67117056u   // 8192*8193 (start of last row within a matrix)
#define DIAG_STRIDE 8194u      // diag element i at i*(MD+1) within a matrix
#define CLCU 16384u            // 2*NN floats of cl/cu before the matrices
#define TOTAL 134266882u       // CLCU + 2*MM
#define BODY_END 134266880u    // TOTAL rounded down to multiple of 8
#define NBODY 16783360u        // BODY_END / 8
#define EPS_ALPHA 1e-5f

struct Relax { float cl, cu, dl, du, bl, bu; };

__device__ __forceinline__ Relax relax(float l, float u)
{
    float den_ul = (u > l)    ? (u - l)    : 1.0f;
    float den_6l = (l < 6.0f) ? (6.0f - l) : 1.0f;
    float u_safe = (u > 0.0f) ? u          : 1.0f;

    bool mA = (u > 0.0f) && (u <= 6.0f) && (l >= 0.0f);
    bool mB = (u > 0.0f) && (u <= 6.0f) && (l <  0.0f);
    bool mC = (u > 6.0f) && (l <= 0.0f);
    bool mD = (u > 6.0f) && (l >  0.0f) && (l <= 6.0f);
    bool mE = (l > 6.0f);

    float alpha_B = (u < -l) ? EPS_ALPHA : 1.0f;
    float lam_B   = u / den_ul;
    float aU_C    = ((u - 6.0f) < (6.0f - l)) ? (6.0f / den_6l) : EPS_ALPHA;
    float aL_C    = (u < -l) ? EPS_ALPHA : (6.0f / u_safe);
    float aU_D    = ((u - 6.0f) < (6.0f - l)) ? 1.0f : EPS_ALPHA;
    float aL_D    = (6.0f - l) / den_ul;

    float fA = mA ? 1.0f : 0.0f;
    float fB = mB ? 1.0f : 0.0f;
    float fC = mC ? 1.0f : 0.0f;
    float fD = mD ? 1.0f : 0.0f;
    float fE = mE ? 1.0f : 0.0f;

    Relax r;
    r.du = fA * 1.0f + fB * lam_B   + fC * aU_C + fD * aU_D;
    r.dl = fA * 1.0f + fB * alpha_B + fC * aL_C + fD * aL_D;
    r.bu = fB * (-lam_B * l)
         + fC * (6.0f * (1.0f - aU_C))
         + fD * (6.0f * (1.0f - aU_D))
         + fE * 6.0f;
    r.bl = fD * (l * (1.0f - aL_D)) + fE * 6.0f;
    r.cu = fA * u + fB * u
         + fC * (6.0f + aU_C * (u - 6.0f))
         + fD * (6.0f + aU_D * (u - 6.0f))
         + fE * 6.0f;
    r.cl = fA * l + fB * (alpha_B * l) + fC * (aL_C * l)
         + fD * l + fE * 6.0f;
    return r;
}

__device__ __forceinline__ float mat_value(unsigned p, bool isL,
                                           const float* __restrict__ lower,
                                           const float* __restrict__ upper)
{
    if (p >= BIAS_START) {
        unsigned col = p - BIAS_START;
        if (col == NN) return 1.0f;           // [-1,-1] corner
        Relax r = relax(lower[col], upper[col]);
        return isL ? r.bl : r.bu;
    }
    unsigned row = p / DIAG_STRIDE;
    if (p == row * DIAG_STRIDE) {
        Relax r = relax(lower[row], upper[row]);
        return isL ? r.dl : r.du;
    }
    return 0.0f;
}

__device__ __forceinline__ float out_value(unsigned oe,
                                           const float* __restrict__ lower,
                                           const float* __restrict__ upper)
{
    if (oe < CLCU) {
        unsigned i = oe & (NN - 1u);
        Relax r = relax(lower[i], upper[i]);
        return (oe < NN) ? r.cl : r.cu;
    }
    unsigned r = oe - CLCU;
    if (r < MM) return mat_value(r, true, lower, upper);
    return mat_value(r - MM, false, lower, upper);
}

// 256-bit global store (sm_100+): one STG.256 per thread per chunk.
__device__ __forceinline__ void st256(float* p,
                                      float a, float b, float c, float d,
                                      float e, float f, float g, float h)
{
    asm volatile("st.global.v8.f32 [%0], {%1,%2,%3,%4,%5,%6,%7,%8};"
                 :: "l"(p),
                    "f"(a), "f"(b), "f"(c), "f"(d),
                    "f"(e), "f"(f), "f"(g), "f"(h)
                 : "memory");
}

// Each thread owns one 32B (8-float) chunk; warp covers 1024B contiguous.
__global__ void relu6_v8(const float* __restrict__ lower,
                         const float* __restrict__ upper,
                         float* __restrict__ out)
{
    unsigned c = blockIdx.x * blockDim.x + threadIdx.x;

    if (c < NBODY) {
        unsigned o = c * 8u;

        // Fast pure-zero test: chunk fully inside one matrix, no diag/bias element.
        unsigned r = o - CLCU;                     // valid when o >= CLCU
        bool inL = (o >= CLCU) & (r + 8u <= MM);
        bool inU = (r >= MM) & (r + 8u <= 2u * MM);
        unsigned p = inU ? (r - MM) : r;
        unsigned q = (p + 7u) / DIAG_STRIDE;       // constant divide
        bool hasDiag = (q * DIAG_STRIDE >= p);     // multiple of 8194 in [p, p+8)
        bool hasBias = (p + 7u >= BIAS_START);

        if ((inL | inU) & !hasDiag & !hasBias) {
            st256(out + o, 0.f, 0.f, 0.f, 0.f, 0.f, 0.f, 0.f, 0.f);
        } else {
            float v[8];
            #pragma unroll
            for (int j = 0; j < 8; ++j)
                v[j] = out_value(o + j, lower, upper);
            st256(out + o, v[0], v[1], v[2], v[3], v[4], v[5], v[6], v[7]);
        }
        return;
    }

    if (c == NBODY) {
        // Tail: TOTAL % 8 == 2
        for (unsigned oe = BODY_END; oe < TOTAL; ++oe)
            out[oe] = out_value(oe, lower, upper);
    }
}

extern "C" void kernel_launch(void* const* d_in, const int* in_sizes, int n_in,
                              void* d_out, int out_size)
{
    const float* lower = (const float*)d_in[0];
    const float* upper = (const float*)d_in[1];
    float* out = (float*)d_out;

    unsigned total_threads = NBODY + 1u;
    unsigned threads = 256u;
    unsigned blocks = (total_threads + threads - 1u) / threads;
    relu6_v8<<<blocks, threads>>>(lower, upper, out);
}